// round 14
// baseline (speedup 1.0000x reference)
#include <cuda_runtime.h>
#include <cuda_bf16.h>
#include <math.h>

#define N_NODES 50000
#define N_EDGES 800000
#define HDIM    128
#define NLAYERS 3
#define NGRAPHS 64
#define BN_EPS  1e-5f
#define NSCANB  ((N_NODES + 255) / 256)   // 196 scan blocks

typedef unsigned long long ull;

// ---------------- scratch (device globals) ----------------------------------
__device__ __align__(16) float g_buf0[N_NODES * HDIM];
__device__ __align__(16) float g_buf1[N_NODES * HDIM];
__device__ int   g_cnt     [N_NODES];
__device__ int   g_rowstart[N_NODES + 1];
__device__ int   g_cursor  [N_NODES];
__device__ int   g_csr     [N_EDGES];
__device__ ull   g_state   [NSCANB];      // lookback scan state (flag<<62 | value)
__device__ float g_invdeg  [N_NODES];
__device__ __align__(16) float g_affa[HDIM];
__device__ __align__(16) float g_affb[HDIM];
__device__ float g_colsum[HDIM];
__device__ float g_colsq [HDIM];
__device__ float g_pool[NGRAPHS];

// ---------------- f32x2 helpers ---------------------------------------------
__device__ __forceinline__ ull fma2(ull a, ull b, ull c) {
    ull d;
    asm("fma.rn.f32x2 %0, %1, %2, %3;" : "=l"(d) : "l"(a), "l"(b), "l"(c));
    return d;
}
__device__ __forceinline__ ull dup2(float x) {
    ull d;
    asm("mov.b64 %0, {%1, %1};" : "=l"(d) : "f"(x));
    return d;
}

// ---------------- launch 0: count (+ state reset + identity affine) ----------
__global__ void count_kernel(const int* __restrict__ ei) {
    int e = blockIdx.x * blockDim.x + threadIdx.x;
    if (e < N_EDGES) atomicAdd(&g_cnt[ei[N_EDGES + e]], 1);
    if (e < NSCANB) g_state[e] = 0ull;
    if (e < HDIM) { g_affa[e] = 1.0f; g_affb[e] = 0.0f; }
}

// ---------------- launch 1: single-pass decoupled-lookback scan --------------
// Also: rowstart/cursor/invdeg, sentinel, and g_cnt reset for next replay.
__global__ void __launch_bounds__(256)
scan_kernel() {
    __shared__ int wtot[8];
    __shared__ int s_prefix;
    const int tid  = threadIdx.x;
    const int lane = tid & 31;
    const int wid  = tid >> 5;
    const int b    = blockIdx.x;
    const int i    = b * 256 + tid;

    int cnt = (i < N_NODES) ? g_cnt[i] : 0;

    // block inclusive scan
    int v = cnt;
#pragma unroll
    for (int off = 1; off < 32; off <<= 1) {
        int n = __shfl_up_sync(0xffffffffu, v, off);
        if (lane >= off) v += n;
    }
    if (lane == 31) wtot[wid] = v;
    __syncthreads();
    if (wid == 0) {
        int t = (lane < 8) ? wtot[lane] : 0;
#pragma unroll
        for (int off = 1; off < 8; off <<= 1) {
            int n = __shfl_up_sync(0xffffffffu, t, off);
            if (lane >= off) t += n;
        }
        if (lane < 8) wtot[lane] = t;
    }
    __syncthreads();
    int incl   = v + ((wid > 0) ? wtot[wid - 1] : 0);
    int btotal = wtot[7];

    // publish AGG (or PREFIX for block 0), then lookback
    if (tid == 0) {
        if (b == 0) {
            atomicExch(&g_state[0], (2ull << 62) | (ull)btotal);
            s_prefix = 0;
        } else {
            atomicExch(&g_state[b], (1ull << 62) | (ull)btotal);
        }
    }
    __syncthreads();
    if (b > 0 && wid == 0) {
        long long prefix = 0;
        int j = b;
        while (true) {
            int idx = j - 1 - lane;
            int flag = 0;
            long long val = 0;
            if (idx >= 0) {
                ull s;
                do { s = atomicOr(&g_state[idx], 0ull); } while ((s >> 62) == 0);
                flag = (int)(s >> 62);
                val  = (long long)(s & 0x3FFFFFFFFFFFFFFFull);
            }
            unsigned pm = __ballot_sync(0xffffffffu, (idx >= 0) && (flag == 2));
            int firstP = pm ? (__ffs(pm) - 1) : 32;
            long long contrib = (idx >= 0 && lane <= firstP) ? val : 0;
#pragma unroll
            for (int off = 16; off; off >>= 1)
                contrib += __shfl_down_sync(0xffffffffu, contrib, off);
            prefix += __shfl_sync(0xffffffffu, contrib, 0);
            if (pm) break;
            j -= 32;
        }
        if (lane == 0) {
            s_prefix = (int)prefix;
            atomicExch(&g_state[b], (2ull << 62) | (ull)(prefix + btotal));
        }
    }
    __syncthreads();

    if (i < N_NODES) {
        int rs = s_prefix + incl - cnt;   // exclusive
        g_rowstart[i] = rs;
        g_cursor[i]   = rs;
        g_invdeg[i]   = 1.0f / fmaxf((float)cnt, 1.0f);
        g_cnt[i]      = 0;                // reset for next replay
    }
    if (b == 0 && tid == 0) g_rowstart[N_NODES] = N_EDGES;
}

// ---------------- launch 2: fill CSR ------------------------------------------
__global__ void fill_kernel(const int* __restrict__ ei) {
    int e = blockIdx.x * blockDim.x + threadIdx.x;
    if (e < N_EDGES) {
        int dst = ei[N_EDGES + e];
        int pos = atomicAdd(&g_cursor[dst], 1);
        g_csr[pos] = ei[e];
    }
}

// ---------------- FUSED gather + dual GEMM + bias + relu + BN stats ----------
// y = relu( mean_nbr(affine(h)) @ Wl^T + affine(h) @ Wr^T + bias );
// affine folded into A-operands (gather result and hprev tile), weights raw.
#define AS_STRIDE 66
#define OFF_SAGG 0                          // 128 * 66
#define OFF_AS   (128 * AS_STRIDE)          // 32 * 66
#define OFF_BS   (OFF_AS + 32 * AS_STRIDE)  // 32 * 132
#define OFF_CS   (OFF_BS + 32 * 132)        // 128
#define OFF_SQ   (OFF_CS + 128)             // 128
#define OFF_SIDX (OFF_SQ + 128)             // 8*32 ints
#define SMEM_FLOATS (OFF_SIDX + 8 * 32)
#define SMEM_BYTES  (SMEM_FLOATS * 4)

__global__ void __launch_bounds__(256)
gemm_fused_kernel(const float* __restrict__ hprev,
                  const float* __restrict__ Wl,
                  const float* __restrict__ Wr,
                  const float* __restrict__ bias,
                  float* __restrict__ yout) {
    extern __shared__ __align__(16) float smem[];
    float* sAggT = smem + OFF_SAGG;
    float* As    = smem + OFF_AS;
    float* Bs    = smem + OFF_BS;
    float* s_cs  = smem + OFF_CS;
    float* s_sq  = smem + OFF_SQ;
    int*   sidx  = (int*)(smem + OFF_SIDX);

    const int tid  = threadIdx.x;
    const int ty   = tid >> 5;
    const int tx   = tid & 31;
    const int row0 = blockIdx.x * 64;

    // ================= phase 1: gather-aggregate into sAggT ==================
    {
        const float4* h4 = (const float4*)hprev;
        int* my_sidx = sidx + ty * 32;
        const float4 a4 = ((const float4*)g_affa)[tx];
        const float4 b4 = ((const float4*)g_affb)[tx];
#pragma unroll 1
        for (int i = 0; i < 8; ++i) {
            int lrow = ty * 8 + i;
            int grow = row0 + lrow;
            int base = 0, deg = 0;
            float id = 0.f;
            if (grow < N_NODES) {
                base = g_rowstart[grow];
                deg  = g_rowstart[grow + 1] - base;
                id   = g_invdeg[grow];
            }
            float4 acc = make_float4(0.f, 0.f, 0.f, 0.f);
            for (int c = 0; c < deg; c += 32) {
                int s = (c + tx < deg) ? g_csr[base + c + tx] : 0;
                my_sidx[tx] = s;
                __syncwarp();
                int m = min(32, deg - c);
#pragma unroll 4
                for (int j = 0; j < m; ++j) {
                    float4 vv = h4[my_sidx[j] * 32 + tx];
                    acc.x += vv.x; acc.y += vv.y; acc.z += vv.z; acc.w += vv.w;
                }
                __syncwarp();
            }
            float bs = (deg > 0) ? 1.0f : 0.0f;
            float4 r;
            r.x = fmaf(acc.x * id, a4.x, b4.x * bs);
            r.y = fmaf(acc.y * id, a4.y, b4.y * bs);
            r.z = fmaf(acc.z * id, a4.z, b4.z * bs);
            r.w = fmaf(acc.w * id, a4.w, b4.w * bs);
            sAggT[(tx * 4 + 0) * AS_STRIDE + lrow] = r.x;
            sAggT[(tx * 4 + 1) * AS_STRIDE + lrow] = r.y;
            sAggT[(tx * 4 + 2) * AS_STRIDE + lrow] = r.z;
            sAggT[(tx * 4 + 3) * AS_STRIDE + lrow] = r.w;
        }
    }
    __syncthreads();

    // ================= phase 2: dual GEMM ====================================
    ull acc2[4][4];
#pragma unroll
    for (int p = 0; p < 4; ++p)
#pragma unroll
        for (int j = 0; j < 4; ++j) acc2[p][j] = 0ull;

#pragma unroll 1
    for (int t = 0; t < 8; ++t) {
        const bool second = (t >= 4);
        const int  kloc   = (t & 3) * 32;
        const float* W = second ? Wr : Wl;

        if (second) {
            // stage affine(hprev) tile
#pragma unroll
            for (int i = 0; i < 2; ++i) {
                int f  = tid + 256 * i;
                int r  = f >> 3;
                int c4 = f & 7;
                int grow = row0 + r;
                float4 v = make_float4(0.f, 0.f, 0.f, 0.f);
                if (grow < N_NODES) {
                    v = *((const float4*)(hprev + (size_t)grow * HDIM + kloc + c4 * 4));
                    float4 aa = ((const float4*)g_affa)[(kloc >> 2) + c4];
                    float4 bb = ((const float4*)g_affb)[(kloc >> 2) + c4];
                    v.x = fmaf(v.x, aa.x, bb.x);
                    v.y = fmaf(v.y, aa.y, bb.y);
                    v.z = fmaf(v.z, aa.z, bb.z);
                    v.w = fmaf(v.w, aa.w, bb.w);
                }
                As[(c4 * 4 + 0) * AS_STRIDE + r] = v.x;
                As[(c4 * 4 + 1) * AS_STRIDE + r] = v.y;
                As[(c4 * 4 + 2) * AS_STRIDE + r] = v.z;
                As[(c4 * 4 + 3) * AS_STRIDE + r] = v.w;
            }
        }
        {
#pragma unroll
            for (int i = 0; i < 4; ++i) {
                int f  = tid + 256 * i;
                int j  = f >> 3;
                int kq = f & 7;
                float4 w = *((const float4*)(W + (size_t)j * HDIM + kloc + kq * 4));
                Bs[(kq * 4 + 0) * 132 + j] = w.x;
                Bs[(kq * 4 + 1) * 132 + j] = w.y;
                Bs[(kq * 4 + 2) * 132 + j] = w.z;
                Bs[(kq * 4 + 3) * 132 + j] = w.w;
            }
        }
        __syncthreads();

        const float* abase = second ? As : (sAggT + (t * 32) * AS_STRIDE);
#pragma unroll
        for (int k = 0; k < 32; ++k) {
            const ull* ap = (const ull*)(abase + k * AS_STRIDE + ty * 8);
            ull a0 = ap[0], a1 = ap[1], a2 = ap[2], a3 = ap[3];
            float4 bv = *((const float4*)(Bs + k * 132 + tx * 4));
            ull b0 = dup2(bv.x), b1 = dup2(bv.y), b2 = dup2(bv.z), b3 = dup2(bv.w);
            acc2[0][0] = fma2(a0, b0, acc2[0][0]);
            acc2[0][1] = fma2(a0, b1, acc2[0][1]);
            acc2[0][2] = fma2(a0, b2, acc2[0][2]);
            acc2[0][3] = fma2(a0, b3, acc2[0][3]);
            acc2[1][0] = fma2(a1, b0, acc2[1][0]);
            acc2[1][1] = fma2(a1, b1, acc2[1][1]);
            acc2[1][2] = fma2(a1, b2, acc2[1][2]);
            acc2[1][3] = fma2(a1, b3, acc2[1][3]);
            acc2[2][0] = fma2(a2, b0, acc2[2][0]);
            acc2[2][1] = fma2(a2, b1, acc2[2][1]);
            acc2[2][2] = fma2(a2, b2, acc2[2][2]);
            acc2[2][3] = fma2(a2, b3, acc2[2][3]);
            acc2[3][0] = fma2(a3, b0, acc2[3][0]);
            acc2[3][1] = fma2(a3, b1, acc2[3][1]);
            acc2[3][2] = fma2(a3, b2, acc2[3][2]);
            acc2[3][3] = fma2(a3, b3, acc2[3][3]);
        }
        __syncthreads();
    }

    // ================= epilogue ==============================================
    const int col = tx * 4;
    float4 bi = *((const float4*)(bias + col));
    float cs[4] = {0.f, 0.f, 0.f, 0.f};
    float sq[4] = {0.f, 0.f, 0.f, 0.f};
#pragma unroll
    for (int p = 0; p < 4; ++p) {
        float lo[4], hi[4];
#pragma unroll
        for (int j = 0; j < 4; ++j) {
            lo[j] = __uint_as_float((unsigned)(acc2[p][j] & 0xffffffffull));
            hi[j] = __uint_as_float((unsigned)(acc2[p][j] >> 32));
        }
        int grow = row0 + ty * 8 + 2 * p;
        if (grow < N_NODES) {
            float4 r;
            r.x = fmaxf(lo[0] + bi.x, 0.f);
            r.y = fmaxf(lo[1] + bi.y, 0.f);
            r.z = fmaxf(lo[2] + bi.z, 0.f);
            r.w = fmaxf(lo[3] + bi.w, 0.f);
            *((float4*)(yout + (size_t)grow * HDIM + col)) = r;
            cs[0] += r.x; sq[0] += r.x * r.x;
            cs[1] += r.y; sq[1] += r.y * r.y;
            cs[2] += r.z; sq[2] += r.z * r.z;
            cs[3] += r.w; sq[3] += r.w * r.w;
        }
        if (grow + 1 < N_NODES) {
            float4 r;
            r.x = fmaxf(hi[0] + bi.x, 0.f);
            r.y = fmaxf(hi[1] + bi.y, 0.f);
            r.z = fmaxf(hi[2] + bi.z, 0.f);
            r.w = fmaxf(hi[3] + bi.w, 0.f);
            *((float4*)(yout + (size_t)(grow + 1) * HDIM + col)) = r;
            cs[0] += r.x; sq[0] += r.x * r.x;
            cs[1] += r.y; sq[1] += r.y * r.y;
            cs[2] += r.z; sq[2] += r.z * r.z;
            cs[3] += r.w; sq[3] += r.w * r.w;
        }
    }
    if (tid < HDIM) { s_cs[tid] = 0.f; s_sq[tid] = 0.f; }
    __syncthreads();
#pragma unroll
    for (int j = 0; j < 4; ++j) {
        atomicAdd(&s_cs[col + j], cs[j]);
        atomicAdd(&s_sq[col + j], sq[j]);
    }
    __syncthreads();
    if (tid < HDIM) {
        atomicAdd(&g_colsum[tid], s_cs[tid]);
        atomicAdd(&g_colsq [tid], s_sq[tid]);
    }
}

// ---------------- BN finalize -> affine (and stats reset) --------------------
__global__ void finalize_kernel(const float* __restrict__ gamma,
                                const float* __restrict__ beta) {
    int j = threadIdx.x;
    if (j >= HDIM) return;
    float s  = g_colsum[j];
    float q  = g_colsq[j];
    float mu  = s / (float)N_NODES;
    float var = q / (float)N_NODES - mu * mu;
    float a = gamma[j] * rsqrtf(var + BN_EPS);
    float b = beta[j] - mu * a;
    g_affa[j] = a;
    g_affb[j] = b;
    g_colsum[j] = 0.f;
    g_colsq [j] = 0.f;
}

// ---------------- pooling fused with FC --------------------------------------
__global__ void pool_kernel(const float* __restrict__ h,
                            const int* __restrict__ batch,
                            const float* __restrict__ fcw) {
    int gt   = blockIdx.x * blockDim.x + threadIdx.x;
    int node = gt >> 5;
    int lane = gt & 31;
    if (node >= N_NODES) return;
    float4 v = ((const float4*)h)[node * 32 + lane];
    float4 a = ((const float4*)g_affa)[lane];
    float4 b = ((const float4*)g_affb)[lane];
    float4 w = ((const float4*)fcw)[lane];
    float d = fmaf(v.x, a.x, b.x) * w.x
            + fmaf(v.y, a.y, b.y) * w.y
            + fmaf(v.z, a.z, b.z) * w.z
            + fmaf(v.w, a.w, b.w) * w.w;
#pragma unroll
    for (int off = 16; off; off >>= 1)
        d += __shfl_down_sync(0xffffffff, d, off);
    if (lane == 0) atomicAdd(&g_pool[batch[node]], d);
}

__global__ void out_kernel(const float* __restrict__ fcb, float* __restrict__ out) {
    int g = threadIdx.x;
    if (g < NGRAPHS) {
        out[g] = 1.0f / (1.0f + expf(-(g_pool[g] + fcb[0])));
        g_pool[g] = 0.0f;   // reset for next replay
    }
}

// ---------------- host launcher (graph-capturable) --------------------------
extern "C" void kernel_launch(void* const* d_in, const int* in_sizes, int n_in,
                              void* d_out, int out_size) {
    const float* x        = (const float*)d_in[0];
    const int*   ei       = (const int*)d_in[1];
    /* d_in[2] edge_attr unused */
    const int*   batch    = (const int*)d_in[3];
    const float* lin_l_w  = (const float*)d_in[4];
    const float* lin_l_b  = (const float*)d_in[5];
    const float* lin_r_w  = (const float*)d_in[6];
    const float* bn_gamma = (const float*)d_in[7];
    const float* bn_beta  = (const float*)d_in[8];
    const float* fc_w     = (const float*)d_in[9];
    const float* fc_b     = (const float*)d_in[10];
    float*       out      = (float*)d_out;

    static int smem_set = 0;
    if (!smem_set) {
        cudaFuncSetAttribute(gemm_fused_kernel,
                             cudaFuncAttributeMaxDynamicSharedMemorySize, SMEM_BYTES);
        smem_set = 1;
    }

    void *p_b0, *p_b1;
    cudaGetSymbolAddress(&p_b0, g_buf0);
    cudaGetSymbolAddress(&p_b1, g_buf1);
    float* bufs[2] = { (float*)p_b0, (float*)p_b1 };

    count_kernel<<<(N_EDGES + 255) / 256, 256>>>(ei);   // 0
    scan_kernel<<<NSCANB, 256>>>();                     // 1
    fill_kernel<<<(N_EDGES + 255) / 256, 256>>>(ei);    // 2

    const float* hprev = x;
    for (int l = 0; l < NLAYERS; ++l) {
        float* yout = bufs[l & 1];
        gemm_fused_kernel<<<(N_NODES + 63) / 64, 256, SMEM_BYTES>>>(  // 3 (l=0)
            hprev,
            lin_l_w + (size_t)l * HDIM * HDIM,
            lin_r_w + (size_t)l * HDIM * HDIM,
            lin_l_b + (size_t)l * HDIM,
            yout);
        finalize_kernel<<<1, HDIM>>>(bn_gamma + (size_t)l * HDIM,
                                     bn_beta  + (size_t)l * HDIM);
        hprev = yout;
    }
    pool_kernel<<<(N_NODES * 32 + 255) / 256, 256>>>(hprev, batch, fc_w);
    out_kernel<<<1, NGRAPHS>>>(fc_b, out);
}

// round 15
// speedup vs baseline: 1.0038x; 1.0038x over previous
#include <cuda_runtime.h>
#include <cuda_bf16.h>
#include <math.h>

#define N_NODES 50000
#define N_EDGES 800000
#define HDIM    128
#define NLAYERS 3
#define NGRAPHS 64
#define BN_EPS  1e-5f
#define NSCANB  ((N_NODES + 255) / 256)   // 196 scan blocks

typedef unsigned long long ull;

// ---------------- scratch (device globals) ----------------------------------
__device__ __align__(16) float g_buf0[N_NODES * HDIM];
__device__ __align__(16) float g_buf1[N_NODES * HDIM];
__device__ int   g_cnt     [N_NODES];
__device__ int   g_rowstart[N_NODES + 1];
__device__ int   g_cursor  [N_NODES];
__device__ int   g_csr     [N_EDGES];
__device__ ull   g_state   [NSCANB];      // lookback scan state (flag<<62 | value)
__device__ float g_invdeg  [N_NODES];
__device__ __align__(16) float g_affa[HDIM];
__device__ __align__(16) float g_affb[HDIM];
__device__ float g_colsum[HDIM];
__device__ float g_colsq [HDIM];
__device__ float g_pool[NGRAPHS];

// ---------------- f32x2 helpers ---------------------------------------------
__device__ __forceinline__ ull fma2(ull a, ull b, ull c) {
    ull d;
    asm("fma.rn.f32x2 %0, %1, %2, %3;" : "=l"(d) : "l"(a), "l"(b), "l"(c));
    return d;
}
__device__ __forceinline__ ull dup2(float x) {
    ull d;
    asm("mov.b64 %0, {%1, %1};" : "=l"(d) : "f"(x));
    return d;
}

// ---------------- launch 0: count (+ state reset + identity affine) ----------
__global__ void count_kernel(const int* __restrict__ ei) {
    int e = blockIdx.x * blockDim.x + threadIdx.x;
    if (e < N_EDGES) atomicAdd(&g_cnt[ei[N_EDGES + e]], 1);
    if (e < NSCANB) g_state[e] = 0ull;
    if (e < HDIM) { g_affa[e] = 1.0f; g_affb[e] = 0.0f; }
}

// ---------------- launch 1: single-pass decoupled-lookback scan --------------
// Also: rowstart/cursor/invdeg, sentinel, and g_cnt reset for next replay.
__global__ void __launch_bounds__(256)
scan_kernel() {
    __shared__ int wtot[8];
    __shared__ int s_prefix;
    const int tid  = threadIdx.x;
    const int lane = tid & 31;
    const int wid  = tid >> 5;
    const int b    = blockIdx.x;
    const int i    = b * 256 + tid;

    int cnt = (i < N_NODES) ? g_cnt[i] : 0;

    // block inclusive scan
    int v = cnt;
#pragma unroll
    for (int off = 1; off < 32; off <<= 1) {
        int n = __shfl_up_sync(0xffffffffu, v, off);
        if (lane >= off) v += n;
    }
    if (lane == 31) wtot[wid] = v;
    __syncthreads();
    if (wid == 0) {
        int t = (lane < 8) ? wtot[lane] : 0;
#pragma unroll
        for (int off = 1; off < 8; off <<= 1) {
            int n = __shfl_up_sync(0xffffffffu, t, off);
            if (lane >= off) t += n;
        }
        if (lane < 8) wtot[lane] = t;
    }
    __syncthreads();
    int incl   = v + ((wid > 0) ? wtot[wid - 1] : 0);
    int btotal = wtot[7];

    // publish AGG (or PREFIX for block 0), then lookback
    if (tid == 0) {
        if (b == 0) {
            atomicExch(&g_state[0], (2ull << 62) | (ull)btotal);
            s_prefix = 0;
        } else {
            atomicExch(&g_state[b], (1ull << 62) | (ull)btotal);
        }
    }
    __syncthreads();
    if (b > 0 && wid == 0) {
        long long prefix = 0;
        int j = b;
        while (true) {
            int idx = j - 1 - lane;
            int flag = 0;
            long long val = 0;
            if (idx >= 0) {
                ull s;
                do { s = atomicOr(&g_state[idx], 0ull); } while ((s >> 62) == 0);
                flag = (int)(s >> 62);
                val  = (long long)(s & 0x3FFFFFFFFFFFFFFFull);
            }
            unsigned pm = __ballot_sync(0xffffffffu, (idx >= 0) && (flag == 2));
            int firstP = pm ? (__ffs(pm) - 1) : 32;
            long long contrib = (idx >= 0 && lane <= firstP) ? val : 0;
#pragma unroll
            for (int off = 16; off; off >>= 1)
                contrib += __shfl_down_sync(0xffffffffu, contrib, off);
            prefix += __shfl_sync(0xffffffffu, contrib, 0);
            if (pm) break;
            j -= 32;
        }
        if (lane == 0) {
            s_prefix = (int)prefix;
            atomicExch(&g_state[b], (2ull << 62) | (ull)(prefix + btotal));
        }
    }
    __syncthreads();

    if (i < N_NODES) {
        int rs = s_prefix + incl - cnt;   // exclusive
        g_rowstart[i] = rs;
        g_cursor[i]   = rs;
        g_invdeg[i]   = 1.0f / fmaxf((float)cnt, 1.0f);
        g_cnt[i]      = 0;                // reset for next replay
    }
    if (b == 0 && tid == 0) g_rowstart[N_NODES] = N_EDGES;
}

// ---------------- launch 2: fill CSR ------------------------------------------
__global__ void fill_kernel(const int* __restrict__ ei) {
    int e = blockIdx.x * blockDim.x + threadIdx.x;
    if (e < N_EDGES) {
        int dst = ei[N_EDGES + e];
        int pos = atomicAdd(&g_cursor[dst], 1);
        g_csr[pos] = ei[e];
    }
}

// ---------------- FUSED gather + dual GEMM + bias + relu + BN stats ----------
// y = relu( mean_nbr(affine(h)) @ Wl^T + affine(h) @ Wr^T + bias );
// affine folded into A-operands (gather result and hprev tile), weights raw.
#define AS_STRIDE 66
#define OFF_SAGG 0                          // 128 * 66
#define OFF_AS   (128 * AS_STRIDE)          // 32 * 66
#define OFF_BS   (OFF_AS + 32 * AS_STRIDE)  // 32 * 132
#define OFF_CS   (OFF_BS + 32 * 132)        // 128
#define OFF_SQ   (OFF_CS + 128)             // 128
#define OFF_SIDX (OFF_SQ + 128)             // 8*32 ints
#define SMEM_FLOATS (OFF_SIDX + 8 * 32)
#define SMEM_BYTES  (SMEM_FLOATS * 4)

__global__ void __launch_bounds__(256)
gemm_fused_kernel(const float* __restrict__ hprev,
                  const float* __restrict__ Wl,
                  const float* __restrict__ Wr,
                  const float* __restrict__ bias,
                  float* __restrict__ yout) {
    extern __shared__ __align__(16) float smem[];
    float* sAggT = smem + OFF_SAGG;
    float* As    = smem + OFF_AS;
    float* Bs    = smem + OFF_BS;
    float* s_cs  = smem + OFF_CS;
    float* s_sq  = smem + OFF_SQ;
    int*   sidx  = (int*)(smem + OFF_SIDX);

    const int tid  = threadIdx.x;
    const int ty   = tid >> 5;
    const int tx   = tid & 31;
    const int row0 = blockIdx.x * 64;

    // ================= phase 1: gather-aggregate into sAggT ==================
    {
        const float4* h4 = (const float4*)hprev;
        int* my_sidx = sidx + ty * 32;
        const float4 a4 = ((const float4*)g_affa)[tx];
        const float4 b4 = ((const float4*)g_affb)[tx];
#pragma unroll 1
        for (int i = 0; i < 8; ++i) {
            int lrow = ty * 8 + i;
            int grow = row0 + lrow;
            int base = 0, deg = 0;
            float id = 0.f;
            if (grow < N_NODES) {
                base = g_rowstart[grow];
                deg  = g_rowstart[grow + 1] - base;
                id   = g_invdeg[grow];
            }
            float4 acc = make_float4(0.f, 0.f, 0.f, 0.f);
            for (int c = 0; c < deg; c += 32) {
                int s = (c + tx < deg) ? g_csr[base + c + tx] : 0;
                my_sidx[tx] = s;
                __syncwarp();
                int m = min(32, deg - c);
#pragma unroll 4
                for (int j = 0; j < m; ++j) {
                    float4 vv = h4[my_sidx[j] * 32 + tx];
                    acc.x += vv.x; acc.y += vv.y; acc.z += vv.z; acc.w += vv.w;
                }
                __syncwarp();
            }
            float bs = (deg > 0) ? 1.0f : 0.0f;
            float4 r;
            r.x = fmaf(acc.x * id, a4.x, b4.x * bs);
            r.y = fmaf(acc.y * id, a4.y, b4.y * bs);
            r.z = fmaf(acc.z * id, a4.z, b4.z * bs);
            r.w = fmaf(acc.w * id, a4.w, b4.w * bs);
            sAggT[(tx * 4 + 0) * AS_STRIDE + lrow] = r.x;
            sAggT[(tx * 4 + 1) * AS_STRIDE + lrow] = r.y;
            sAggT[(tx * 4 + 2) * AS_STRIDE + lrow] = r.z;
            sAggT[(tx * 4 + 3) * AS_STRIDE + lrow] = r.w;
        }
    }
    __syncthreads();

    // ================= phase 2: dual GEMM ====================================
    ull acc2[4][4];
#pragma unroll
    for (int p = 0; p < 4; ++p)
#pragma unroll
        for (int j = 0; j < 4; ++j) acc2[p][j] = 0ull;

#pragma unroll 1
    for (int t = 0; t < 8; ++t) {
        const bool second = (t >= 4);
        const int  kloc   = (t & 3) * 32;
        const float* W = second ? Wr : Wl;

        if (second) {
            // stage affine(hprev) tile
#pragma unroll
            for (int i = 0; i < 2; ++i) {
                int f  = tid + 256 * i;
                int r  = f >> 3;
                int c4 = f & 7;
                int grow = row0 + r;
                float4 v = make_float4(0.f, 0.f, 0.f, 0.f);
                if (grow < N_NODES) {
                    v = *((const float4*)(hprev + (size_t)grow * HDIM + kloc + c4 * 4));
                    float4 aa = ((const float4*)g_affa)[(kloc >> 2) + c4];
                    float4 bb = ((const float4*)g_affb)[(kloc >> 2) + c4];
                    v.x = fmaf(v.x, aa.x, bb.x);
                    v.y = fmaf(v.y, aa.y, bb.y);
                    v.z = fmaf(v.z, aa.z, bb.z);
                    v.w = fmaf(v.w, aa.w, bb.w);
                }
                As[(c4 * 4 + 0) * AS_STRIDE + r] = v.x;
                As[(c4 * 4 + 1) * AS_STRIDE + r] = v.y;
                As[(c4 * 4 + 2) * AS_STRIDE + r] = v.z;
                As[(c4 * 4 + 3) * AS_STRIDE + r] = v.w;
            }
        }
        {
#pragma unroll
            for (int i = 0; i < 4; ++i) {
                int f  = tid + 256 * i;
                int j  = f >> 3;
                int kq = f & 7;
                float4 w = *((const float4*)(W + (size_t)j * HDIM + kloc + kq * 4));
                Bs[(kq * 4 + 0) * 132 + j] = w.x;
                Bs[(kq * 4 + 1) * 132 + j] = w.y;
                Bs[(kq * 4 + 2) * 132 + j] = w.z;
                Bs[(kq * 4 + 3) * 132 + j] = w.w;
            }
        }
        __syncthreads();

        const float* abase = second ? As : (sAggT + (t * 32) * AS_STRIDE);
#pragma unroll
        for (int k = 0; k < 32; ++k) {
            const ull* ap = (const ull*)(abase + k * AS_STRIDE + ty * 8);
            ull a0 = ap[0], a1 = ap[1], a2 = ap[2], a3 = ap[3];
            float4 bv = *((const float4*)(Bs + k * 132 + tx * 4));
            ull b0 = dup2(bv.x), b1 = dup2(bv.y), b2 = dup2(bv.z), b3 = dup2(bv.w);
            acc2[0][0] = fma2(a0, b0, acc2[0][0]);
            acc2[0][1] = fma2(a0, b1, acc2[0][1]);
            acc2[0][2] = fma2(a0, b2, acc2[0][2]);
            acc2[0][3] = fma2(a0, b3, acc2[0][3]);
            acc2[1][0] = fma2(a1, b0, acc2[1][0]);
            acc2[1][1] = fma2(a1, b1, acc2[1][1]);
            acc2[1][2] = fma2(a1, b2, acc2[1][2]);
            acc2[1][3] = fma2(a1, b3, acc2[1][3]);
            acc2[2][0] = fma2(a2, b0, acc2[2][0]);
            acc2[2][1] = fma2(a2, b1, acc2[2][1]);
            acc2[2][2] = fma2(a2, b2, acc2[2][2]);
            acc2[2][3] = fma2(a2, b3, acc2[2][3]);
            acc2[3][0] = fma2(a3, b0, acc2[3][0]);
            acc2[3][1] = fma2(a3, b1, acc2[3][1]);
            acc2[3][2] = fma2(a3, b2, acc2[3][2]);
            acc2[3][3] = fma2(a3, b3, acc2[3][3]);
        }
        __syncthreads();
    }

    // ================= epilogue ==============================================
    const int col = tx * 4;
    float4 bi = *((const float4*)(bias + col));
    float cs[4] = {0.f, 0.f, 0.f, 0.f};
    float sq[4] = {0.f, 0.f, 0.f, 0.f};
#pragma unroll
    for (int p = 0; p < 4; ++p) {
        float lo[4], hi[4];
#pragma unroll
        for (int j = 0; j < 4; ++j) {
            lo[j] = __uint_as_float((unsigned)(acc2[p][j] & 0xffffffffull));
            hi[j] = __uint_as_float((unsigned)(acc2[p][j] >> 32));
        }
        int grow = row0 + ty * 8 + 2 * p;
        if (grow < N_NODES) {
            float4 r;
            r.x = fmaxf(lo[0] + bi.x, 0.f);
            r.y = fmaxf(lo[1] + bi.y, 0.f);
            r.z = fmaxf(lo[2] + bi.z, 0.f);
            r.w = fmaxf(lo[3] + bi.w, 0.f);
            *((float4*)(yout + (size_t)grow * HDIM + col)) = r;
            cs[0] += r.x; sq[0] += r.x * r.x;
            cs[1] += r.y; sq[1] += r.y * r.y;
            cs[2] += r.z; sq[2] += r.z * r.z;
            cs[3] += r.w; sq[3] += r.w * r.w;
        }
        if (grow + 1 < N_NODES) {
            float4 r;
            r.x = fmaxf(hi[0] + bi.x, 0.f);
            r.y = fmaxf(hi[1] + bi.y, 0.f);
            r.z = fmaxf(hi[2] + bi.z, 0.f);
            r.w = fmaxf(hi[3] + bi.w, 0.f);
            *((float4*)(yout + (size_t)(grow + 1) * HDIM + col)) = r;
            cs[0] += r.x; sq[0] += r.x * r.x;
            cs[1] += r.y; sq[1] += r.y * r.y;
            cs[2] += r.z; sq[2] += r.z * r.z;
            cs[3] += r.w; sq[3] += r.w * r.w;
        }
    }
    if (tid < HDIM) { s_cs[tid] = 0.f; s_sq[tid] = 0.f; }
    __syncthreads();
#pragma unroll
    for (int j = 0; j < 4; ++j) {
        atomicAdd(&s_cs[col + j], cs[j]);
        atomicAdd(&s_sq[col + j], sq[j]);
    }
    __syncthreads();
    if (tid < HDIM) {
        atomicAdd(&g_colsum[tid], s_cs[tid]);
        atomicAdd(&g_colsq [tid], s_sq[tid]);
    }
}

// ---------------- BN finalize -> affine (and stats reset) --------------------
__global__ void finalize_kernel(const float* __restrict__ gamma,
                                const float* __restrict__ beta) {
    int j = threadIdx.x;
    if (j >= HDIM) return;
    float s  = g_colsum[j];
    float q  = g_colsq[j];
    float mu  = s / (float)N_NODES;
    float var = q / (float)N_NODES - mu * mu;
    float a = gamma[j] * rsqrtf(var + BN_EPS);
    float b = beta[j] - mu * a;
    g_affa[j] = a;
    g_affb[j] = b;
    g_colsum[j] = 0.f;
    g_colsq [j] = 0.f;
}

// ---------------- pooling fused with FC --------------------------------------
__global__ void pool_kernel(const float* __restrict__ h,
                            const int* __restrict__ batch,
                            const float* __restrict__ fcw) {
    int gt   = blockIdx.x * blockDim.x + threadIdx.x;
    int node = gt >> 5;
    int lane = gt & 31;
    if (node >= N_NODES) return;
    float4 v = ((const float4*)h)[node * 32 + lane];
    float4 a = ((const float4*)g_affa)[lane];
    float4 b = ((const float4*)g_affb)[lane];
    float4 w = ((const float4*)fcw)[lane];
    float d = fmaf(v.x, a.x, b.x) * w.x
            + fmaf(v.y, a.y, b.y) * w.y
            + fmaf(v.z, a.z, b.z) * w.z
            + fmaf(v.w, a.w, b.w) * w.w;
#pragma unroll
    for (int off = 16; off; off >>= 1)
        d += __shfl_down_sync(0xffffffff, d, off);
    if (lane == 0) atomicAdd(&g_pool[batch[node]], d);
}

__global__ void out_kernel(const float* __restrict__ fcb, float* __restrict__ out) {
    int g = threadIdx.x;
    if (g < NGRAPHS) {
        out[g] = 1.0f / (1.0f + expf(-(g_pool[g] + fcb[0])));
        g_pool[g] = 0.0f;   // reset for next replay
    }
}

// ---------------- host launcher (graph-capturable) --------------------------
extern "C" void kernel_launch(void* const* d_in, const int* in_sizes, int n_in,
                              void* d_out, int out_size) {
    const float* x        = (const float*)d_in[0];
    const int*   ei       = (const int*)d_in[1];
    /* d_in[2] edge_attr unused */
    const int*   batch    = (const int*)d_in[3];
    const float* lin_l_w  = (const float*)d_in[4];
    const float* lin_l_b  = (const float*)d_in[5];
    const float* lin_r_w  = (const float*)d_in[6];
    const float* bn_gamma = (const float*)d_in[7];
    const float* bn_beta  = (const float*)d_in[8];
    const float* fc_w     = (const float*)d_in[9];
    const float* fc_b     = (const float*)d_in[10];
    float*       out      = (float*)d_out;

    static int smem_set = 0;
    if (!smem_set) {
        cudaFuncSetAttribute(gemm_fused_kernel,
                             cudaFuncAttributeMaxDynamicSharedMemorySize, SMEM_BYTES);
        smem_set = 1;
    }

    void *p_b0, *p_b1;
    cudaGetSymbolAddress(&p_b0, g_buf0);
    cudaGetSymbolAddress(&p_b1, g_buf1);
    float* bufs[2] = { (float*)p_b0, (float*)p_b1 };

    count_kernel<<<(N_EDGES + 255) / 256, 256>>>(ei);   // 0
    scan_kernel<<<NSCANB, 256>>>();                     // 1
    fill_kernel<<<(N_EDGES + 255) / 256, 256>>>(ei);    // 2

    const float* hprev = x;
    for (int l = 0; l < NLAYERS; ++l) {
        float* yout = bufs[l & 1];
        gemm_fused_kernel<<<(N_NODES + 63) / 64, 256, SMEM_BYTES>>>(  // 3 (l=0)
            hprev,
            lin_l_w + (size_t)l * HDIM * HDIM,
            lin_r_w + (size_t)l * HDIM * HDIM,
            lin_l_b + (size_t)l * HDIM,
            yout);
        finalize_kernel<<<1, HDIM>>>(bn_gamma + (size_t)l * HDIM,
                                     bn_beta  + (size_t)l * HDIM);
        hprev = yout;
    }
    pool_kernel<<<(N_NODES * 32 + 255) / 256, 256>>>(hprev, batch, fc_w);
    out_kernel<<<1, NGRAPHS>>>(fc_b, out);
}